// round 10
// baseline (speedup 1.0000x reference)
#include <cuda_runtime.h>
#include <cuda_bf16.h>

typedef unsigned int u32;
typedef unsigned long long u64;

#define NBLK  128
#define NTHR  512
#define ROWS  64
#define HPAD  132
#define NSTEP 49
#define TSTRIDE 288   // tile row stride in bytes (72 words == 8 mod 32 -> bank-clean LDS.64)

// ---- dynamic smem layout (float offsets) ----
#define F_XPP   0        // 128  xpp[2][64] decoder partials
#define F_GP    128      // 512  gp4[u] = (wir, wiz, win, bnh)
#define F_GB    640      // 512  gb4[u] = (br, bz, bni, 0)
#define F_DW1   1152     // 16
#define F_DB0   1168     // 16
#define F_DB1   1184     // 1 (pad to 1216)
#define F_HHI   1216     // 64*72 = 4608 floats (bf16 tile, permuted k-pairs)
#define F_HLO   5824     // 4608
#define F_HS    10432    // 16*512 hold slots
#define F_HA    18624    // 64*132 encoder scratch
#define SMEM_FLOATS 27072
#define SMEM_BYTES  (SMEM_FLOATS*4)

// GRU B fragments (weights): [g][ut][k][lane] uint4 = (bh0, bh1, bl0, bl1)
__device__ uint4 g_wfrag[3 * 16 * 8 * 32];
// decoder B fragments: [nt][k][lane] uint4
__device__ uint4 g_dfrag[2 * 8 * 32];

#define MMA4(c, a0, a1, a2, a3, b0v, b1v) asm volatile( \
    "mma.sync.aligned.m16n8k16.row.col.f32.bf16.bf16.f32 " \
    "{%0,%1,%2,%3}, {%4,%5,%6,%7}, {%8,%9}, {%0,%1,%2,%3};" \
    : "+f"((c)[0]), "+f"((c)[1]), "+f"((c)[2]), "+f"((c)[3]) \
    : "r"(a0), "r"(a1), "r"(a2), "r"(a3), "r"(b0v), "r"(b1v))

#define BARG(gid) asm volatile("bar.sync %0, %1;" :: "r"((gid) + 1), "r"(256) : "memory")

__device__ __forceinline__ float tanha(float x) {
    float y;
    asm("tanh.approx.f32 %0, %1;" : "=f"(y) : "f"(x));
    return y;
}
__device__ __forceinline__ float sigm(float x) {
    return fmaf(0.5f, tanha(0.5f * x), 0.5f);
}
__device__ __forceinline__ u32 pack_bf2(__nv_bfloat16 lo, __nv_bfloat16 hi) {
    return ((u32)__bfloat16_as_ushort(hi) << 16) | (u32)__bfloat16_as_ushort(lo);
}
// packed = {hi = bf16(vhi), lo = bf16(vlo)}
__device__ __forceinline__ u32 cvt_bf16x2(float vhi, float vlo) {
    u32 r;
    asm("cvt.rn.bf16x2.f32 %0, %1, %2;" : "=r"(r) : "f"(vhi), "f"(vlo));
    return r;
}
// position of k-pair p (0..7) within a 16-k block (pairs p and p+4 adjacent)
__device__ __forceinline__ int pair_pos(int p) {
    return 2 * (p & 3) + ((p >> 2) & 1);
}

// ---------------- weight repack ----------------
__global__ void repack(const float* __restrict__ whh, const float* __restrict__ dw0) {
    int idx = blockIdx.x * blockDim.x + threadIdx.x;
    if (idx < 12288) {
        int lane = idx & 31;
        int k    = (idx >> 5) & 7;
        int ut   = (idx >> 8) & 15;
        int g    = idx >> 12;          // 0..2
        int n    = ut * 8 + (lane >> 2);
        int k0   = k * 16 + (lane & 3) * 2;
        const float* wr = whh + (g * 128 + n) * 128;
        float v0 = wr[k0],     v1 = wr[k0 + 1];
        float v2 = wr[k0 + 8], v3 = wr[k0 + 9];
        __nv_bfloat16 h0 = __float2bfloat16(v0), h1 = __float2bfloat16(v1);
        __nv_bfloat16 h2 = __float2bfloat16(v2), h3 = __float2bfloat16(v3);
        u32 bh0 = pack_bf2(h0, h1), bh1 = pack_bf2(h2, h3);
        u32 bl0 = pack_bf2(__float2bfloat16(v0 - __bfloat162float(h0)),
                           __float2bfloat16(v1 - __bfloat162float(h1)));
        u32 bl1 = pack_bf2(__float2bfloat16(v2 - __bfloat162float(h2)),
                           __float2bfloat16(v3 - __bfloat162float(h3)));
        g_wfrag[idx] = make_uint4(bh0, bh1, bl0, bl1);
    } else if (idx < 12800) {
        int local = idx - 12288;
        int lane = local & 31;
        int k    = (local >> 5) & 7;
        int nt   = local >> 8;         // 0..1
        int n    = nt * 8 + (lane >> 2);
        int k0   = k * 16 + (lane & 3) * 2;
        float v0 = dw0[k0 * 16 + n],       v1 = dw0[(k0 + 1) * 16 + n];
        float v2 = dw0[(k0 + 8) * 16 + n], v3 = dw0[(k0 + 9) * 16 + n];
        __nv_bfloat16 h0 = __float2bfloat16(v0), h1 = __float2bfloat16(v1);
        __nv_bfloat16 h2 = __float2bfloat16(v2), h3 = __float2bfloat16(v3);
        u32 bh0 = pack_bf2(h0, h1), bh1 = pack_bf2(h2, h3);
        u32 bl0 = pack_bf2(__float2bfloat16(v0 - __bfloat162float(h0)),
                           __float2bfloat16(v1 - __bfloat162float(h1)));
        u32 bl1 = pack_bf2(__float2bfloat16(v2 - __bfloat162float(h2)),
                           __float2bfloat16(v3 - __bfloat162float(h3)));
        g_dfrag[local] = make_uint4(bh0, bh1, bl0, bl1);
    }
}

// one 128->128 encoder layer (reads/writes ha), scalar fp32
__device__ __forceinline__ void enc_layer128(const float* __restrict__ w,
                                             const float* __restrict__ b,
                                             float* ha, int p, int t, bool relu_on) {
    float acc[4][4];
    #pragma unroll
    for (int uu = 0; uu < 4; ++uu)
        #pragma unroll
        for (int m = 0; m < 4; ++m) acc[uu][m] = 0.0f;
    const float4* w4 = (const float4*)w;
    for (int k4 = 0; k4 < 32; ++k4) {
        float xa[4][4];
        #pragma unroll
        for (int m = 0; m < 4; ++m) {
            float4 v = *(const float4*)&ha[(p + 16*m)*HPAD + k4*4];
            xa[m][0] = v.x; xa[m][1] = v.y; xa[m][2] = v.z; xa[m][3] = v.w;
        }
        #pragma unroll
        for (int kk = 0; kk < 4; ++kk) {
            float4 wv = __ldg(&w4[(k4*4 + kk)*32 + t]);
            #pragma unroll
            for (int m = 0; m < 4; ++m) {
                acc[0][m] = fmaf(wv.x, xa[m][kk], acc[0][m]);
                acc[1][m] = fmaf(wv.y, xa[m][kk], acc[1][m]);
                acc[2][m] = fmaf(wv.z, xa[m][kk], acc[2][m]);
                acc[3][m] = fmaf(wv.w, xa[m][kk], acc[3][m]);
            }
        }
    }
    __syncthreads();
    #pragma unroll
    for (int uu = 0; uu < 4; ++uu) {
        int u = t*4 + uu;
        float bv = __ldg(&b[u]);
        #pragma unroll
        for (int m = 0; m < 4; ++m) {
            float v = acc[uu][m] + bv;
            ha[(p + 16*m)*HPAD + u] = relu_on ? fmaxf(v, 0.0f) : v;
        }
    }
    __syncthreads();
}

__global__ void __launch_bounds__(NTHR, 1)
gru_kernel(const float* __restrict__ x,
           const float* __restrict__ ew0, const float* __restrict__ eb0,
           const float* __restrict__ ew1, const float* __restrict__ eb1,
           const float* __restrict__ ew2, const float* __restrict__ eb2,
           const float* __restrict__ wih, const float* __restrict__ whh,
           const float* __restrict__ bih, const float* __restrict__ bhh,
           const float* __restrict__ dw0, const float* __restrict__ db0,
           const float* __restrict__ dw1, const float* __restrict__ db1,
           float* __restrict__ out) {
    extern __shared__ float sm[];
    float*  xpp  = sm + F_XPP;
    float4* gp4  = (float4*)(sm + F_GP);
    float4* gb4  = (float4*)(sm + F_GB);
    float*  dw1s = sm + F_DW1;
    float*  db0s = sm + F_DB0;
    char*   hhi  = (char*)(sm + F_HHI);
    char*   hlo  = (char*)(sm + F_HLO);
    float*  hs   = sm + F_HS;
    float*  ha   = sm + F_HA;

    const int tid  = threadIdx.x;
    const int wid  = tid >> 5;
    const int lane = tid & 31;
    const int row0 = blockIdx.x * ROWS;

    // ---- small smem init ----
    for (int j = tid; j < 128; j += NTHR) {
        gp4[j] = make_float4(wih[j], wih[128 + j], wih[256 + j], bhh[256 + j]);
        gb4[j] = make_float4(bih[j] + bhh[j], bih[128 + j] + bhh[128 + j], bih[256 + j], 0.0f);
    }
    if (tid < 16) { dw1s[tid] = dw1[tid]; db0s[tid] = db0[tid]; }
    if (tid == 0) sm[F_DB1] = db1[0];
    if (tid < ROWS) out[(u64)(row0 + tid)*50] = 0.0f;

    // ---- encoder (scalar fp32) ----
    {
        const int p = tid & 15, t = tid >> 4;
        float acc[4][4];
        #pragma unroll
        for (int uu = 0; uu < 4; ++uu)
            #pragma unroll
            for (int m = 0; m < 4; ++m) acc[uu][m] = 0.0f;
        const float4* x4  = (const float4*)x;
        const float4* w04 = (const float4*)ew0;
        for (int k4 = 0; k4 < 64; ++k4) {
            float xa[4][4];
            #pragma unroll
            for (int m = 0; m < 4; ++m) {
                float4 v = __ldg(&x4[(u64)(row0 + p + 16*m)*64 + k4]);
                xa[m][0] = v.x; xa[m][1] = v.y; xa[m][2] = v.z; xa[m][3] = v.w;
            }
            #pragma unroll
            for (int kk = 0; kk < 4; ++kk) {
                float4 wv = __ldg(&w04[(k4*4 + kk)*32 + t]);
                #pragma unroll
                for (int m = 0; m < 4; ++m) {
                    acc[0][m] = fmaf(wv.x, xa[m][kk], acc[0][m]);
                    acc[1][m] = fmaf(wv.y, xa[m][kk], acc[1][m]);
                    acc[2][m] = fmaf(wv.z, xa[m][kk], acc[2][m]);
                    acc[3][m] = fmaf(wv.w, xa[m][kk], acc[3][m]);
                }
            }
        }
        __syncthreads();
        #pragma unroll
        for (int uu = 0; uu < 4; ++uu) {
            int u = t*4 + uu;
            float bv = __ldg(&eb0[u]);
            #pragma unroll
            for (int m = 0; m < 4; ++m)
                ha[(p + 16*m)*HPAD + u] = fmaxf(acc[uu][m] + bv, 0.0f);
        }
        __syncthreads();
        enc_layer128(ew1, eb1, ha, p, t, true);
        enc_layer128(ew2, eb2, ha, p, t, false);
    }

    const int grp = wid >> 3;       // row group: rows [grp*32, grp*32+32)
    const int wm  = wid & 7;        // unit-block warp index within group
    const int gr0 = grp * 32;

    // ---- h0: ha -> permuted bf16 hi/lo tiles + hold slots ----
    for (int j = tid; j < 8192; j += NTHR) {
        int r = j >> 7, u = j & 127;
        float v = ha[r*HPAD + u];
        int pu  = u >> 1;
        u32 off = (u32)(r*TSTRIDE + (pu >> 3)*32 + pair_pos(pu & 7)*4 + (u & 1)*2);
        __nv_bfloat16 bh = __float2bfloat16(v);
        __nv_bfloat16 bl = __float2bfloat16(v - __bfloat162float(bh));
        *(__nv_bfloat16*)(hhi + off) = bh;
        *(__nv_bfloat16*)(hlo + off) = bl;
    }
    #pragma unroll
    for (int mt = 0; mt < 2; ++mt)
        #pragma unroll
        for (int ut = 0; ut < 2; ++ut)
            #pragma unroll
            for (int rh = 0; rh < 2; ++rh)
                #pragma unroll
                for (int j = 0; j < 2; ++j) {
                    int u = wm*16 + ut*8 + (lane & 3)*2 + j;
                    int r = gr0 + mt*16 + (lane >> 2) + rh*8;
                    hs[(((mt*2 + ut)*2 + rh)*2 + j)*512 + tid] = ha[r*HPAD + u];
                }
    __syncthreads();
    const float db1v = sm[F_DB1];

    float accG[2][2][3][4];   // [mt][ut][gate][q]
    float accD[4];

    // phase A: GRU MMA + fused decoder MMA over this group's 32 rows
    auto phaseA = [&]() {
        #pragma unroll
        for (int mt = 0; mt < 2; ++mt)
            #pragma unroll
            for (int ut = 0; ut < 2; ++ut)
                #pragma unroll
                for (int g = 0; g < 3; ++g)
                    #pragma unroll
                    for (int q = 0; q < 4; ++q) accG[mt][ut][g][q] = 0.0f;
        if (wm < 4) { accD[0] = accD[1] = accD[2] = accD[3] = 0.0f; }

        #pragma unroll 2
        for (int k = 0; k < 8; ++k) {
            #pragma unroll
            for (int mt = 0; mt < 2; ++mt) {
                u32 aoff = (u32)((gr0 + mt*16 + (lane >> 2))*TSTRIDE + k*32 + (lane & 3)*8);
                uint2 h0 = *(const uint2*)(hhi + aoff);
                uint2 h8 = *(const uint2*)(hhi + aoff + 8*TSTRIDE);
                uint2 l0 = *(const uint2*)(hlo + aoff);
                uint2 l8 = *(const uint2*)(hlo + aoff + 8*TSTRIDE);
                #pragma unroll
                for (int ut = 0; ut < 2; ++ut)
                    #pragma unroll
                    for (int g = 0; g < 3; ++g) {
                        uint4 w = __ldg(&g_wfrag[((g*16 + wm*2 + ut)*8 + k)*32 + lane]);
                        MMA4(accG[mt][ut][g], h0.x, h8.x, h0.y, h8.y, w.x, w.y);
                        MMA4(accG[mt][ut][g], l0.x, l8.x, l0.y, l8.y, w.x, w.y);
                        MMA4(accG[mt][ut][g], h0.x, h8.x, h0.y, h8.y, w.z, w.w);
                    }
                if (wm < 4 && mt == (wm >> 1)) {
                    uint4 d = __ldg(&g_dfrag[((wm & 1)*8 + k)*32 + lane]);
                    MMA4(accD, h0.x, h8.x, h0.y, h8.y, d.x, d.y);
                    MMA4(accD, l0.x, l8.x, l0.y, l8.y, d.x, d.y);
                    MMA4(accD, h0.x, h8.x, h0.y, h8.y, d.z, d.w);
                }
            }
        }
        // decoder partial reduce -> xpp
        if (wm < 4) {
            int i0 = (wm & 1)*8 + (lane & 3)*2;
            float w1a = dw1s[i0], w1b = dw1s[i0 + 1];
            float b0a = db0s[i0], b0b = db0s[i0 + 1];
            float v0 = fmaxf(accD[0] + b0a, 0.0f)*w1a + fmaxf(accD[1] + b0b, 0.0f)*w1b;
            float v8 = fmaxf(accD[2] + b0a, 0.0f)*w1a + fmaxf(accD[3] + b0b, 0.0f)*w1b;
            v0 += __shfl_xor_sync(0xffffffffu, v0, 1);
            v0 += __shfl_xor_sync(0xffffffffu, v0, 2);
            v8 += __shfl_xor_sync(0xffffffffu, v8, 1);
            v8 += __shfl_xor_sync(0xffffffffu, v8, 2);
            if ((lane & 3) == 0) {
                int r0 = gr0 + (wm >> 1)*16 + (lane >> 2);
                xpp[(wm & 1)*64 + r0]     = v0;
                xpp[(wm & 1)*64 + r0 + 8] = v8;
            }
        }
    };

    // phase B: epilogue -> new h tiles + hold slots; writes out col s (s>=1)
    auto phaseB = [&](int s) {
        float xpv[2][2];
        #pragma unroll
        for (int mt = 0; mt < 2; ++mt)
            #pragma unroll
            for (int rh = 0; rh < 2; ++rh) {
                int r = gr0 + mt*16 + (lane >> 2) + rh*8;
                xpv[mt][rh] = (s > 0) ? (xpp[r] + xpp[64 + r] + db1v) : 0.0f;
            }
        if (wm == 0 && s > 0 && (lane & 3) == 0) {
            #pragma unroll
            for (int mt = 0; mt < 2; ++mt)
                #pragma unroll
                for (int rh = 0; rh < 2; ++rh) {
                    int r = gr0 + mt*16 + (lane >> 2) + rh*8;
                    out[(u64)(row0 + r)*50 + s] = xpv[mt][rh];
                }
        }
        #pragma unroll
        for (int mt = 0; mt < 2; ++mt)
            #pragma unroll
            for (int ut = 0; ut < 2; ++ut) {
                int u0 = wm*16 + ut*8 + (lane & 3)*2;
                float4 P0 = gp4[u0],     Q0 = gb4[u0];
                float4 P1 = gp4[u0 + 1], Q1 = gb4[u0 + 1];
                float hh[2][2];
                #pragma unroll
                for (int rh = 0; rh < 2; ++rh)
                    #pragma unroll
                    for (int j = 0; j < 2; ++j) {
                        float4 P = j ? P1 : P0;
                        float4 Q = j ? Q1 : Q0;
                        int q = rh*2 + j;
                        int idx = ((mt*2 + ut)*2 + rh)*2 + j;
                        float xp   = xpv[mt][rh];
                        float hold = hs[idx*512 + tid];
                        float rg = sigm(accG[mt][ut][0][q] + fmaf(xp, P.x, Q.x));
                        float zg = sigm(accG[mt][ut][1][q] + fmaf(xp, P.y, Q.y));
                        float ng = tanha(fmaf(xp, P.z, Q.z) + rg*(accG[mt][ut][2][q] + P.w));
                        float h  = (1.0f - zg)*ng + zg*hold;
                        hs[idx*512 + tid] = h;
                        hh[rh][j] = h;
                    }
                int pu7  = ut*4 + (lane & 3);
                u32 base = (u32)(wm*32 + pair_pos(pu7)*4);
                #pragma unroll
                for (int rh = 0; rh < 2; ++rh) {
                    int r = gr0 + mt*16 + (lane >> 2) + rh*8;
                    u32 off = (u32)(r*TSTRIDE) + base;
                    u32 ph = cvt_bf16x2(hh[rh][1], hh[rh][0]);
                    float f0 = __uint_as_float(ph << 16);
                    float f1 = __uint_as_float(ph & 0xffff0000u);
                    u32 pl = cvt_bf16x2(hh[rh][1] - f1, hh[rh][0] - f0);
                    *(u32*)(hhi + off) = ph;
                    *(u32*)(hlo + off) = pl;
                }
            }
    };

    if (grp == 0) {
        phaseA();
        for (int s = 0; s < NSTEP; ++s) {
            BARG(0);
            phaseB(s);
            BARG(0);
            if (s < NSTEP - 1) phaseA();
        }
    } else {
        for (int s = 0; s < NSTEP; ++s) {
            phaseA();
            BARG(1);
            phaseB(s);
            BARG(1);
        }
    }

    // ---- final decoder: dec(h_49) -> out col 49 ----
    if (wm < 4) {
        float dacc[4] = {0.0f, 0.0f, 0.0f, 0.0f};
        int mt = wm >> 1;
        #pragma unroll 2
        for (int k = 0; k < 8; ++k) {
            u32 aoff = (u32)((gr0 + mt*16 + (lane >> 2))*TSTRIDE + k*32 + (lane & 3)*8);
            uint2 h0 = *(const uint2*)(hhi + aoff);
            uint2 h8 = *(const uint2*)(hhi + aoff + 8*TSTRIDE);
            uint2 l0 = *(const uint2*)(hlo + aoff);
            uint2 l8 = *(const uint2*)(hlo + aoff + 8*TSTRIDE);
            uint4 d = __ldg(&g_dfrag[((wm & 1)*8 + k)*32 + lane]);
            MMA4(dacc, h0.x, h8.x, h0.y, h8.y, d.x, d.y);
            MMA4(dacc, l0.x, l8.x, l0.y, l8.y, d.x, d.y);
            MMA4(dacc, h0.x, h8.x, h0.y, h8.y, d.z, d.w);
        }
        int i0 = (wm & 1)*8 + (lane & 3)*2;
        float w1a = dw1s[i0], w1b = dw1s[i0 + 1];
        float b0a = db0s[i0], b0b = db0s[i0 + 1];
        float v0 = fmaxf(dacc[0] + b0a, 0.0f)*w1a + fmaxf(dacc[1] + b0b, 0.0f)*w1b;
        float v8 = fmaxf(dacc[2] + b0a, 0.0f)*w1a + fmaxf(dacc[3] + b0b, 0.0f)*w1b;
        v0 += __shfl_xor_sync(0xffffffffu, v0, 1);
        v0 += __shfl_xor_sync(0xffffffffu, v0, 2);
        v8 += __shfl_xor_sync(0xffffffffu, v8, 1);
        v8 += __shfl_xor_sync(0xffffffffu, v8, 2);
        if ((lane & 3) == 0) {
            int r0 = gr0 + (wm >> 1)*16 + (lane >> 2);
            xpp[(wm & 1)*64 + r0]     = v0;
            xpp[(wm & 1)*64 + r0 + 8] = v8;
        }
    }
    BARG(grp);
    if (wm == 0 && (lane & 3) == 0) {
        #pragma unroll
        for (int mt = 0; mt < 2; ++mt)
            #pragma unroll
            for (int rh = 0; rh < 2; ++rh) {
                int r = gr0 + mt*16 + (lane >> 2) + rh*8;
                out[(u64)(row0 + r)*50 + NSTEP] = xpp[r] + xpp[64 + r] + db1v;
            }
    }
}

extern "C" void kernel_launch(void* const* d_in, const int* in_sizes, int n_in,
                              void* d_out, int out_size) {
    (void)in_sizes; (void)n_in; (void)out_size;
    const float* x   = (const float*)d_in[0];
    const float* ew0 = (const float*)d_in[1];
    const float* eb0 = (const float*)d_in[2];
    const float* ew1 = (const float*)d_in[3];
    const float* eb1 = (const float*)d_in[4];
    const float* ew2 = (const float*)d_in[5];
    const float* eb2 = (const float*)d_in[6];
    const float* wih = (const float*)d_in[7];
    const float* whh = (const float*)d_in[8];
    const float* bih = (const float*)d_in[9];
    const float* bhh = (const float*)d_in[10];
    const float* dw0 = (const float*)d_in[11];
    const float* db0 = (const float*)d_in[12];
    const float* dw1 = (const float*)d_in[13];
    const float* db1 = (const float*)d_in[14];
    float* out = (float*)d_out;

    cudaFuncSetAttribute(gru_kernel, cudaFuncAttributeMaxDynamicSharedMemorySize, SMEM_BYTES);

    repack<<<25, 512>>>(whh, dw0);
    gru_kernel<<<NBLK, NTHR, SMEM_BYTES>>>(x, ew0, eb0, ew1, eb1, ew2, eb2,
                                           wih, whh, bih, bhh, dw0, db0, dw1, db1, out);
}

// round 11
// speedup vs baseline: 1.1892x; 1.1892x over previous
#include <cuda_runtime.h>
#include <cuda_bf16.h>

typedef unsigned int u32;
typedef unsigned long long u64;

#define NBLK  128
#define NTHR  512
#define ROWS  64
#define HPAD  132
#define NSTEP 49

// ---- dynamic smem layout (float offsets) ----
#define F_XPS   0        // 64
#define F_WIHS  64       // 384
#define F_BIHS  448      // 384
#define F_BHHS  832      // 384
#define F_DW1   1216     // 16
#define F_DB0   1232     // 16
#define F_DB1   1248     // 1 (pad to 1280)
#define F_HHI   1280     // bf16 [64][136] = 4352 floats
#define F_HLO   5632     // 4352
#define F_HS    9984     // 16*512 per-thread hold slots
#define F_HA    18176    // 64*132 encoder scratch
#define SMEM_FLOATS 26624
#define SMEM_BYTES  (SMEM_FLOATS*4)

// GRU A fragments: [prec][g][wm][k][lane] as uint4
__device__ uint4 g_wfrag[2 * 3 * 8 * 8 * 32];
// decoder A fragments: [prec][k][lane] as uint4 (m16 x k128)
__device__ uint4 g_dfrag[2 * 8 * 32];

#define MMA(c, a, b0v, b1v) asm volatile( \
    "mma.sync.aligned.m16n8k16.row.col.f32.bf16.bf16.f32 " \
    "{%0,%1,%2,%3}, {%4,%5,%6,%7}, {%8,%9}, {%0,%1,%2,%3};" \
    : "+f"((c)[0]), "+f"((c)[1]), "+f"((c)[2]), "+f"((c)[3]) \
    : "r"((a).x), "r"((a).y), "r"((a).z), "r"((a).w), "r"(b0v), "r"(b1v))

#define BARG(gid) asm volatile("bar.sync %0, %1;" :: "r"((gid) + 1), "r"(256) : "memory")

__device__ __forceinline__ float tanha(float x) {
    float y;
    asm("tanh.approx.f32 %0, %1;" : "=f"(y) : "f"(x));
    return y;
}
__device__ __forceinline__ float sigm(float x) {
    return fmaf(0.5f, tanha(0.5f * x), 0.5f);
}
__device__ __forceinline__ u32 pack_bf2(__nv_bfloat16 lo, __nv_bfloat16 hi) {
    return ((u32)__bfloat16_as_ushort(hi) << 16) | (u32)__bfloat16_as_ushort(lo);
}

// ---------------- weight repack ----------------
__global__ void repack(const float* __restrict__ whh, const float* __restrict__ dw0) {
    int idx = blockIdx.x * blockDim.x + threadIdx.x;
    if (idx < 12288) {
        int lane = idx & 31;
        int k    = (idx >> 5) & 7;
        int wm   = (idx >> 8) & 7;
        int gp   = idx >> 11;          // 0..5
        int g    = gp % 3;
        int prec = gp / 3;
        int row  = g * 128 + wm * 16 + (lane >> 2);
        int k0   = k * 16 + (lane & 3) * 2;
        u32 o[4];
        #pragma unroll
        for (int q = 0; q < 4; ++q) {
            int rr = row + 8 * (q & 1);
            int kk = k0 + 8 * (q >> 1);
            float v0 = whh[rr * 128 + kk];
            float v1 = whh[rr * 128 + kk + 1];
            __nv_bfloat16 h0 = __float2bfloat16(v0);
            __nv_bfloat16 h1 = __float2bfloat16(v1);
            if (prec == 0) o[q] = pack_bf2(h0, h1);
            else o[q] = pack_bf2(__float2bfloat16(v0 - __bfloat162float(h0)),
                                 __float2bfloat16(v1 - __bfloat162float(h1)));
        }
        g_wfrag[idx] = make_uint4(o[0], o[1], o[2], o[3]);
    } else if (idx < 12800) {
        int local = idx - 12288;
        int lane = local & 31;
        int k    = (local >> 5) & 7;
        int prec = local >> 8;
        int row  = lane >> 2;
        int k0   = k * 16 + (lane & 3) * 2;
        u32 o[4];
        #pragma unroll
        for (int q = 0; q < 4; ++q) {
            int rr = row + 8 * (q & 1);
            int kk = k0 + 8 * (q >> 1);
            float v0 = dw0[kk * 16 + rr];
            float v1 = dw0[(kk + 1) * 16 + rr];
            __nv_bfloat16 h0 = __float2bfloat16(v0);
            __nv_bfloat16 h1 = __float2bfloat16(v1);
            if (prec == 0) o[q] = pack_bf2(h0, h1);
            else o[q] = pack_bf2(__float2bfloat16(v0 - __bfloat162float(h0)),
                                 __float2bfloat16(v1 - __bfloat162float(h1)));
        }
        g_dfrag[local] = make_uint4(o[0], o[1], o[2], o[3]);
    }
}

// one 128->128 encoder layer (reads/writes ha), scalar fp32
__device__ __forceinline__ void enc_layer128(const float* __restrict__ w,
                                             const float* __restrict__ b,
                                             float* ha, int p, int t, bool relu_on) {
    float acc[4][4];
    #pragma unroll
    for (int uu = 0; uu < 4; ++uu)
        #pragma unroll
        for (int m = 0; m < 4; ++m) acc[uu][m] = 0.0f;
    const float4* w4 = (const float4*)w;
    for (int k4 = 0; k4 < 32; ++k4) {
        float xa[4][4];
        #pragma unroll
        for (int m = 0; m < 4; ++m) {
            float4 v = *(const float4*)&ha[(p + 16*m)*HPAD + k4*4];
            xa[m][0] = v.x; xa[m][1] = v.y; xa[m][2] = v.z; xa[m][3] = v.w;
        }
        #pragma unroll
        for (int kk = 0; kk < 4; ++kk) {
            float4 wv = __ldg(&w4[(k4*4 + kk)*32 + t]);
            #pragma unroll
            for (int m = 0; m < 4; ++m) {
                acc[0][m] = fmaf(wv.x, xa[m][kk], acc[0][m]);
                acc[1][m] = fmaf(wv.y, xa[m][kk], acc[1][m]);
                acc[2][m] = fmaf(wv.z, xa[m][kk], acc[2][m]);
                acc[3][m] = fmaf(wv.w, xa[m][kk], acc[3][m]);
            }
        }
    }
    __syncthreads();
    #pragma unroll
    for (int uu = 0; uu < 4; ++uu) {
        int u = t*4 + uu;
        float bv = __ldg(&b[u]);
        #pragma unroll
        for (int m = 0; m < 4; ++m) {
            float v = acc[uu][m] + bv;
            ha[(p + 16*m)*HPAD + u] = relu_on ? fmaxf(v, 0.0f) : v;
        }
    }
    __syncthreads();
}

__global__ void __launch_bounds__(NTHR, 1)
gru_kernel(const float* __restrict__ x,
           const float* __restrict__ ew0, const float* __restrict__ eb0,
           const float* __restrict__ ew1, const float* __restrict__ eb1,
           const float* __restrict__ ew2, const float* __restrict__ eb2,
           const float* __restrict__ wih, const float* __restrict__ whh,
           const float* __restrict__ bih, const float* __restrict__ bhh,
           const float* __restrict__ dw0, const float* __restrict__ db0,
           const float* __restrict__ dw1, const float* __restrict__ db1,
           float* __restrict__ out) {
    extern __shared__ float sm[];
    float* xps  = sm + F_XPS;
    float* wihs = sm + F_WIHS;
    float* bihs = sm + F_BIHS;
    float* bhhs = sm + F_BHHS;
    float* dw1s = sm + F_DW1;
    float* db0s = sm + F_DB0;
    char*  hhi  = (char*)(sm + F_HHI);   // bf16 [r][136]
    char*  hlo  = (char*)(sm + F_HLO);
    float* hs   = sm + F_HS;             // hold slots [16][512]
    float* ha   = sm + F_HA;

    const int tid  = threadIdx.x;
    const int wid  = tid >> 5;
    const int lane = tid & 31;
    const int row0 = blockIdx.x * ROWS;

    // ---- small smem init ----
    for (int j = tid; j < 384; j += NTHR) {
        wihs[j] = wih[j]; bihs[j] = bih[j]; bhhs[j] = bhh[j];
    }
    if (tid < 16) { dw1s[tid] = dw1[tid]; db0s[tid] = db0[tid]; }
    if (tid == 0) sm[F_DB1] = db1[0];
    if (tid < ROWS) {
        xps[tid] = 0.0f;
        out[(u64)(row0 + tid)*50] = 0.0f;
    }

    // ---- encoder (scalar fp32) ----
    {
        const int p = tid & 15, t = tid >> 4;
        float acc[4][4];
        #pragma unroll
        for (int uu = 0; uu < 4; ++uu)
            #pragma unroll
            for (int m = 0; m < 4; ++m) acc[uu][m] = 0.0f;
        const float4* x4  = (const float4*)x;
        const float4* w04 = (const float4*)ew0;
        for (int k4 = 0; k4 < 64; ++k4) {
            float xa[4][4];
            #pragma unroll
            for (int m = 0; m < 4; ++m) {
                float4 v = __ldg(&x4[(u64)(row0 + p + 16*m)*64 + k4]);
                xa[m][0] = v.x; xa[m][1] = v.y; xa[m][2] = v.z; xa[m][3] = v.w;
            }
            #pragma unroll
            for (int kk = 0; kk < 4; ++kk) {
                float4 wv = __ldg(&w04[(k4*4 + kk)*32 + t]);
                #pragma unroll
                for (int m = 0; m < 4; ++m) {
                    acc[0][m] = fmaf(wv.x, xa[m][kk], acc[0][m]);
                    acc[1][m] = fmaf(wv.y, xa[m][kk], acc[1][m]);
                    acc[2][m] = fmaf(wv.z, xa[m][kk], acc[2][m]);
                    acc[3][m] = fmaf(wv.w, xa[m][kk], acc[3][m]);
                }
            }
        }
        __syncthreads();
        #pragma unroll
        for (int uu = 0; uu < 4; ++uu) {
            int u = t*4 + uu;
            float bv = __ldg(&eb0[u]);
            #pragma unroll
            for (int m = 0; m < 4; ++m)
                ha[(p + 16*m)*HPAD + u] = fmaxf(acc[uu][m] + bv, 0.0f);
        }
        __syncthreads();
        enc_layer128(ew1, eb1, ha, p, t, true);
        enc_layer128(ew2, eb2, ha, p, t, false);
    }

    const int grp   = wid >> 3;     // row group: rows [grp*32, grp*32+32)
    const int wm    = wid & 7;      // unit block (16 units, all 3 gates)
    const int gr0   = grp * 32;

    // ---- h0: ha -> bf16 hi/lo tiles + hold slots ----
    for (int j = tid; j < 8192; j += NTHR) {
        int r = j >> 7, u = j & 127;
        float v = ha[r*HPAD + u];
        __nv_bfloat16 bh = __float2bfloat16(v);
        __nv_bfloat16 bl = __float2bfloat16(v - __bfloat162float(bh));
        *(__nv_bfloat16*)(hhi + r*272 + u*2) = bh;
        *(__nv_bfloat16*)(hlo + r*272 + u*2) = bl;
    }
    #pragma unroll
    for (int i = 0; i < 2; ++i)
        #pragma unroll
        for (int nt = 0; nt < 4; ++nt)
            #pragma unroll
            for (int j = 0; j < 2; ++j) {
                int u = wm*16 + (lane >> 2) + 8*i;
                int r = gr0 + nt*8 + (lane & 3)*2 + j;
                hs[(i*8 + nt*2 + j)*512 + tid] = ha[r*HPAD + u];
            }
    __syncthreads();
    const float db1v = sm[F_DB1];
    const uint4* wf = g_wfrag;

    // decoder (warps wm<4 of each group): reads tiles of own rows -> out col + xps
    auto decoder = [&](int col) {
        float dacc[4] = {0.0f, 0.0f, 0.0f, 0.0f};
        #pragma unroll
        for (int k = 0; k < 8; ++k) {
            int r = gr0 + wm*8 + (lane >> 2);
            int off = r*272 + k*32 + (lane & 3)*4;
            u32 b0 = *(const u32*)(hhi + off);
            u32 b1 = *(const u32*)(hhi + off + 16);
            u32 c0 = *(const u32*)(hlo + off);
            u32 c1 = *(const u32*)(hlo + off + 16);
            uint4 ah = __ldg(&g_dfrag[k*32 + lane]);
            uint4 al = __ldg(&g_dfrag[256 + k*32 + lane]);
            MMA(dacc, ah, b0, b1);
            MMA(dacc, ah, c0, c1);
            MMA(dacc, al, b0, b1);
        }
        int i = lane >> 2;
        float w1a = dw1s[i], w1b = dw1s[i + 8];
        float b0a = db0s[i], b0b = db0s[i + 8];
        float v0 = fmaxf(dacc[0] + b0a, 0.0f)*w1a + fmaxf(dacc[2] + b0b, 0.0f)*w1b;
        float v1 = fmaxf(dacc[1] + b0a, 0.0f)*w1a + fmaxf(dacc[3] + b0b, 0.0f)*w1b;
        v0 += __shfl_xor_sync(0xffffffffu, v0, 4);
        v0 += __shfl_xor_sync(0xffffffffu, v0, 8);
        v0 += __shfl_xor_sync(0xffffffffu, v0, 16);
        v1 += __shfl_xor_sync(0xffffffffu, v1, 4);
        v1 += __shfl_xor_sync(0xffffffffu, v1, 8);
        v1 += __shfl_xor_sync(0xffffffffu, v1, 16);
        if (lane < 4) {
            int r0 = gr0 + wm*8 + lane*2;
            float o0 = v0 + db1v;
            float o1 = v1 + db1v;
            out[(u64)(row0 + r0)*50 + col] = o0;
            out[(u64)(row0 + r0 + 1)*50 + col] = o1;
            xps[r0]     = o0;
            xps[r0 + 1] = o1;
        }
    };

    float acc[3][4][4];

    // phase A: decoder (s>=1) + GRU MMA over this group's 32 rows
    auto phaseA = [&](int s) {
        if (s > 0 && wm < 4) decoder(s);
        #pragma unroll
        for (int g = 0; g < 3; ++g)
            #pragma unroll
            for (int nt = 0; nt < 4; ++nt)
                #pragma unroll
                for (int q = 0; q < 4; ++q) acc[g][nt][q] = 0.0f;
        #pragma unroll 2
        for (int k = 0; k < 8; ++k) {
            u32 bh[4][2], bl[4][2];
            #pragma unroll
            for (int nt = 0; nt < 4; ++nt) {
                int r = gr0 + nt*8 + (lane >> 2);
                int off = r*272 + k*32 + (lane & 3)*4;
                bh[nt][0] = *(const u32*)(hhi + off);
                bh[nt][1] = *(const u32*)(hhi + off + 16);
                bl[nt][0] = *(const u32*)(hlo + off);
                bl[nt][1] = *(const u32*)(hlo + off + 16);
            }
            #pragma unroll
            for (int g = 0; g < 3; ++g) {
                uint4 ah = __ldg(&wf[(g*8 + wm)*256 + k*32 + lane]);
                uint4 al = __ldg(&wf[6144 + (g*8 + wm)*256 + k*32 + lane]);
                #pragma unroll
                for (int nt = 0; nt < 4; ++nt) {
                    MMA(acc[g][nt], ah, bh[nt][0], bh[nt][1]);
                    MMA(acc[g][nt], ah, bl[nt][0], bl[nt][1]);
                    MMA(acc[g][nt], al, bh[nt][0], bh[nt][1]);
                }
            }
        }
    };

    // phase B: epilogue -> new h, write tiles + hold slots (group rows only)
    auto phaseB = [&]() {
        #pragma unroll
        for (int i = 0; i < 2; ++i) {
            int u = wm*16 + (lane >> 2) + 8*i;
            float wir = wihs[u], wiz = wihs[128 + u], win = wihs[256 + u];
            float br  = bihs[u]       + bhhs[u];
            float bz  = bihs[128 + u] + bhhs[128 + u];
            float bni = bihs[256 + u];
            float bnh = bhhs[256 + u];
            #pragma unroll
            for (int nt = 0; nt < 4; ++nt) {
                #pragma unroll
                for (int j = 0; j < 2; ++j) {
                    int r = gr0 + nt*8 + (lane & 3)*2 + j;
                    int q = 2*i + j;
                    int hidx = (i*8 + nt*2 + j)*512 + tid;
                    float xp   = xps[r];
                    float hold = hs[hidx];
                    float rg = sigm(acc[0][nt][q] + fmaf(xp, wir, br));
                    float zg = sigm(acc[1][nt][q] + fmaf(xp, wiz, bz));
                    float ng = tanha(fmaf(xp, win, bni) + rg*(acc[2][nt][q] + bnh));
                    float h  = (1.0f - zg)*ng + zg*hold;
                    hs[hidx] = h;
                    __nv_bfloat16 bhv = __float2bfloat16(h);
                    __nv_bfloat16 blv = __float2bfloat16(h - __bfloat162float(bhv));
                    *(__nv_bfloat16*)(hhi + r*272 + u*2) = bhv;
                    *(__nv_bfloat16*)(hlo + r*272 + u*2) = blv;
                }
            }
        }
    };

    // ---- antiphase scheduling ----
    // g0 runs phaseA(0) while g1 waits at the block barrier. Afterwards:
    //   g0 cadence: [B(s); bar0; A(s+1); bar0]
    //   g1 cadence: [A(s); bar1; B(s); bar1]
    // so g0's epilogue overlaps g1's MMA and vice versa.
    if (grp == 0) phaseA(0);
    __syncthreads();

    if (grp == 0) {
        for (int s = 0; s < NSTEP; ++s) {
            phaseB();
            BARG(0);
            if (s < NSTEP - 1) phaseA(s + 1);
            BARG(0);
        }
        if (wm < 4) decoder(NSTEP);
    } else {
        for (int s = 0; s < NSTEP; ++s) {
            phaseA(s);
            BARG(1);
            phaseB();
            BARG(1);
        }
        if (wm < 4) decoder(NSTEP);
    }
}

extern "C" void kernel_launch(void* const* d_in, const int* in_sizes, int n_in,
                              void* d_out, int out_size) {
    (void)in_sizes; (void)n_in; (void)out_size;
    const float* x   = (const float*)d_in[0];
    const float* ew0 = (const float*)d_in[1];
    const float* eb0 = (const float*)d_in[2];
    const float* ew1 = (const float*)d_in[3];
    const float* eb1 = (const float*)d_in[4];
    const float* ew2 = (const float*)d_in[5];
    const float* eb2 = (const float*)d_in[6];
    const float* wih = (const float*)d_in[7];
    const float* whh = (const float*)d_in[8];
    const float* bih = (const float*)d_in[9];
    const float* bhh = (const float*)d_in[10];
    const float* dw0 = (const float*)d_in[11];
    const float* db0 = (const float*)d_in[12];
    const float* dw1 = (const float*)d_in[13];
    const float* db1 = (const float*)d_in[14];
    float* out = (float*)d_out;

    cudaFuncSetAttribute(gru_kernel, cudaFuncAttributeMaxDynamicSharedMemorySize, SMEM_BYTES);

    repack<<<25, 512>>>(whh, dw0);
    gru_kernel<<<NBLK, NTHR, SMEM_BYTES>>>(x, ew0, eb0, ew1, eb1, ew2, eb2,
                                           wih, whh, bih, bhh, dw0, db0, dw1, db1, out);
}

// round 12
// speedup vs baseline: 1.1992x; 1.0084x over previous
#include <cuda_runtime.h>
#include <cuda_bf16.h>

typedef unsigned int u32;
typedef unsigned long long u64;

#define NBLK  128
#define NTHR  512
#define ROWS  64
#define HPAD  132
#define NSTEP 49

// ---- dynamic smem layout (float offsets) ----
#define F_XPS   0        // 64
#define F_WIHS  64       // 384
#define F_BIHS  448      // 384
#define F_BHHS  832      // 384
#define F_DW1   1216     // 16
#define F_DB0   1232     // 16
#define F_DB1   1248     // 1 (pad to 1280)
#define F_HHI   1280     // bf16 [64][136] = 4352 floats
#define F_HLO   5632     // 4352
#define F_HS    9984     // 16*512 per-thread hold slots
#define F_WS    18176    // staged hi-weights: 6144+256 uint4 = 25600 floats
                         // (encoder scratch ha aliases the first 8448 floats here)
#define SMEM_FLOATS 43776
#define SMEM_BYTES  (SMEM_FLOATS*4)

// GRU A fragments: [prec][g][wm][k][lane] as uint4 (prec0=hi at [0,6144), prec1=lo)
__device__ uint4 g_wfrag[2 * 3 * 8 * 8 * 32];
// decoder A fragments: [prec][k][lane] as uint4 (m16 x k128)
__device__ uint4 g_dfrag[2 * 8 * 32];

#define MMA(c, a, b0v, b1v) asm volatile( \
    "mma.sync.aligned.m16n8k16.row.col.f32.bf16.bf16.f32 " \
    "{%0,%1,%2,%3}, {%4,%5,%6,%7}, {%8,%9}, {%0,%1,%2,%3};" \
    : "+f"((c)[0]), "+f"((c)[1]), "+f"((c)[2]), "+f"((c)[3]) \
    : "r"((a).x), "r"((a).y), "r"((a).z), "r"((a).w), "r"(b0v), "r"(b1v))

#define BARG(gid) asm volatile("bar.sync %0, %1;" :: "r"((gid) + 1), "r"(256) : "memory")

__device__ __forceinline__ float tanha(float x) {
    float y;
    asm("tanh.approx.f32 %0, %1;" : "=f"(y) : "f"(x));
    return y;
}
__device__ __forceinline__ float sigm(float x) {
    return fmaf(0.5f, tanha(0.5f * x), 0.5f);
}
__device__ __forceinline__ u32 pack_bf2(__nv_bfloat16 lo, __nv_bfloat16 hi) {
    return ((u32)__bfloat16_as_ushort(hi) << 16) | (u32)__bfloat16_as_ushort(lo);
}

// ---------------- weight repack ----------------
__global__ void repack(const float* __restrict__ whh, const float* __restrict__ dw0) {
    int idx = blockIdx.x * blockDim.x + threadIdx.x;
    if (idx < 12288) {
        int lane = idx & 31;
        int k    = (idx >> 5) & 7;
        int wm   = (idx >> 8) & 7;
        int gp   = idx >> 11;          // 0..5
        int g    = gp % 3;
        int prec = gp / 3;
        int row  = g * 128 + wm * 16 + (lane >> 2);
        int k0   = k * 16 + (lane & 3) * 2;
        u32 o[4];
        #pragma unroll
        for (int q = 0; q < 4; ++q) {
            int rr = row + 8 * (q & 1);
            int kk = k0 + 8 * (q >> 1);
            float v0 = whh[rr * 128 + kk];
            float v1 = whh[rr * 128 + kk + 1];
            __nv_bfloat16 h0 = __float2bfloat16(v0);
            __nv_bfloat16 h1 = __float2bfloat16(v1);
            if (prec == 0) o[q] = pack_bf2(h0, h1);
            else o[q] = pack_bf2(__float2bfloat16(v0 - __bfloat162float(h0)),
                                 __float2bfloat16(v1 - __bfloat162float(h1)));
        }
        g_wfrag[idx] = make_uint4(o[0], o[1], o[2], o[3]);
    } else if (idx < 12800) {
        int local = idx - 12288;
        int lane = local & 31;
        int k    = (local >> 5) & 7;
        int prec = local >> 8;
        int row  = lane >> 2;
        int k0   = k * 16 + (lane & 3) * 2;
        u32 o[4];
        #pragma unroll
        for (int q = 0; q < 4; ++q) {
            int rr = row + 8 * (q & 1);
            int kk = k0 + 8 * (q >> 1);
            float v0 = dw0[kk * 16 + rr];
            float v1 = dw0[(kk + 1) * 16 + rr];
            __nv_bfloat16 h0 = __float2bfloat16(v0);
            __nv_bfloat16 h1 = __float2bfloat16(v1);
            if (prec == 0) o[q] = pack_bf2(h0, h1);
            else o[q] = pack_bf2(__float2bfloat16(v0 - __bfloat162float(h0)),
                                 __float2bfloat16(v1 - __bfloat162float(h1)));
        }
        g_dfrag[local] = make_uint4(o[0], o[1], o[2], o[3]);
    }
}

// one 128->128 encoder layer (reads/writes ha), scalar fp32
__device__ __forceinline__ void enc_layer128(const float* __restrict__ w,
                                             const float* __restrict__ b,
                                             float* ha, int p, int t, bool relu_on) {
    float acc[4][4];
    #pragma unroll
    for (int uu = 0; uu < 4; ++uu)
        #pragma unroll
        for (int m = 0; m < 4; ++m) acc[uu][m] = 0.0f;
    const float4* w4 = (const float4*)w;
    for (int k4 = 0; k4 < 32; ++k4) {
        float xa[4][4];
        #pragma unroll
        for (int m = 0; m < 4; ++m) {
            float4 v = *(const float4*)&ha[(p + 16*m)*HPAD + k4*4];
            xa[m][0] = v.x; xa[m][1] = v.y; xa[m][2] = v.z; xa[m][3] = v.w;
        }
        #pragma unroll
        for (int kk = 0; kk < 4; ++kk) {
            float4 wv = __ldg(&w4[(k4*4 + kk)*32 + t]);
            #pragma unroll
            for (int m = 0; m < 4; ++m) {
                acc[0][m] = fmaf(wv.x, xa[m][kk], acc[0][m]);
                acc[1][m] = fmaf(wv.y, xa[m][kk], acc[1][m]);
                acc[2][m] = fmaf(wv.z, xa[m][kk], acc[2][m]);
                acc[3][m] = fmaf(wv.w, xa[m][kk], acc[3][m]);
            }
        }
    }
    __syncthreads();
    #pragma unroll
    for (int uu = 0; uu < 4; ++uu) {
        int u = t*4 + uu;
        float bv = __ldg(&b[u]);
        #pragma unroll
        for (int m = 0; m < 4; ++m) {
            float v = acc[uu][m] + bv;
            ha[(p + 16*m)*HPAD + u] = relu_on ? fmaxf(v, 0.0f) : v;
        }
    }
    __syncthreads();
}

__global__ void __launch_bounds__(NTHR, 1)
gru_kernel(const float* __restrict__ x,
           const float* __restrict__ ew0, const float* __restrict__ eb0,
           const float* __restrict__ ew1, const float* __restrict__ eb1,
           const float* __restrict__ ew2, const float* __restrict__ eb2,
           const float* __restrict__ wih, const float* __restrict__ whh,
           const float* __restrict__ bih, const float* __restrict__ bhh,
           const float* __restrict__ dw0, const float* __restrict__ db0,
           const float* __restrict__ dw1, const float* __restrict__ db1,
           float* __restrict__ out) {
    extern __shared__ float sm[];
    float* xps  = sm + F_XPS;
    float* wihs = sm + F_WIHS;
    float* bihs = sm + F_BIHS;
    float* bhhs = sm + F_BHHS;
    float* dw1s = sm + F_DW1;
    float* db0s = sm + F_DB0;
    char*  hhi  = (char*)(sm + F_HHI);   // bf16 [r][136]
    char*  hlo  = (char*)(sm + F_HLO);
    float* hs   = sm + F_HS;             // hold slots [16][512]
    uint4* ws4  = (uint4*)(sm + F_WS);   // staged hi fragments (after encoder)
    float* ha   = sm + F_WS;             // encoder scratch aliases weight area

    const int tid  = threadIdx.x;
    const int wid  = tid >> 5;
    const int lane = tid & 31;
    const int row0 = blockIdx.x * ROWS;

    // ---- small smem init ----
    for (int j = tid; j < 384; j += NTHR) {
        wihs[j] = wih[j]; bihs[j] = bih[j]; bhhs[j] = bhh[j];
    }
    if (tid < 16) { dw1s[tid] = dw1[tid]; db0s[tid] = db0[tid]; }
    if (tid == 0) sm[F_DB1] = db1[0];
    if (tid < ROWS) {
        xps[tid] = 0.0f;
        out[(u64)(row0 + tid)*50] = 0.0f;
    }

    // ---- encoder (scalar fp32) ----
    {
        const int p = tid & 15, t = tid >> 4;
        float acc[4][4];
        #pragma unroll
        for (int uu = 0; uu < 4; ++uu)
            #pragma unroll
            for (int m = 0; m < 4; ++m) acc[uu][m] = 0.0f;
        const float4* x4  = (const float4*)x;
        const float4* w04 = (const float4*)ew0;
        for (int k4 = 0; k4 < 64; ++k4) {
            float xa[4][4];
            #pragma unroll
            for (int m = 0; m < 4; ++m) {
                float4 v = __ldg(&x4[(u64)(row0 + p + 16*m)*64 + k4]);
                xa[m][0] = v.x; xa[m][1] = v.y; xa[m][2] = v.z; xa[m][3] = v.w;
            }
            #pragma unroll
            for (int kk = 0; kk < 4; ++kk) {
                float4 wv = __ldg(&w04[(k4*4 + kk)*32 + t]);
                #pragma unroll
                for (int m = 0; m < 4; ++m) {
                    acc[0][m] = fmaf(wv.x, xa[m][kk], acc[0][m]);
                    acc[1][m] = fmaf(wv.y, xa[m][kk], acc[1][m]);
                    acc[2][m] = fmaf(wv.z, xa[m][kk], acc[2][m]);
                    acc[3][m] = fmaf(wv.w, xa[m][kk], acc[3][m]);
                }
            }
        }
        __syncthreads();
        #pragma unroll
        for (int uu = 0; uu < 4; ++uu) {
            int u = t*4 + uu;
            float bv = __ldg(&eb0[u]);
            #pragma unroll
            for (int m = 0; m < 4; ++m)
                ha[(p + 16*m)*HPAD + u] = fmaxf(acc[uu][m] + bv, 0.0f);
        }
        __syncthreads();
        enc_layer128(ew1, eb1, ha, p, t, true);
        enc_layer128(ew2, eb2, ha, p, t, false);
    }

    const int grp   = wid >> 3;     // row group: rows [grp*32, grp*32+32)
    const int wm    = wid & 7;      // unit block (16 units, all 3 gates)
    const int gr0   = grp * 32;

    // ---- h0: ha -> bf16 hi/lo tiles + hold slots ----
    for (int j = tid; j < 8192; j += NTHR) {
        int r = j >> 7, u = j & 127;
        float v = ha[r*HPAD + u];
        __nv_bfloat16 bh = __float2bfloat16(v);
        __nv_bfloat16 bl = __float2bfloat16(v - __bfloat162float(bh));
        *(__nv_bfloat16*)(hhi + r*272 + u*2) = bh;
        *(__nv_bfloat16*)(hlo + r*272 + u*2) = bl;
    }
    #pragma unroll
    for (int i = 0; i < 2; ++i)
        #pragma unroll
        for (int nt = 0; nt < 4; ++nt)
            #pragma unroll
            for (int j = 0; j < 2; ++j) {
                int u = wm*16 + (lane >> 2) + 8*i;
                int r = gr0 + nt*8 + (lane & 3)*2 + j;
                hs[(i*8 + nt*2 + j)*512 + tid] = ha[r*HPAD + u];
            }
    __syncthreads();   // all reads of ha done; weight staging may overwrite it

    // ---- stage hi-weight fragments into smem (once, reused 49 steps) ----
    for (int j = tid; j < 6144; j += NTHR) ws4[j] = __ldg(&g_wfrag[j]);
    for (int j = tid; j < 256; j += NTHR)  ws4[6144 + j] = __ldg(&g_dfrag[j]);
    __syncthreads();

    const float db1v = sm[F_DB1];
    const uint4* wf = g_wfrag;

    // decoder (warps wm<4 of each group): reads tiles of own rows -> out col + xps
    auto decoder = [&](int col) {
        float dacc[4] = {0.0f, 0.0f, 0.0f, 0.0f};
        #pragma unroll
        for (int k = 0; k < 8; ++k) {
            int r = gr0 + wm*8 + (lane >> 2);
            int off = r*272 + k*32 + (lane & 3)*4;
            u32 b0 = *(const u32*)(hhi + off);
            u32 b1 = *(const u32*)(hhi + off + 16);
            u32 c0 = *(const u32*)(hlo + off);
            u32 c1 = *(const u32*)(hlo + off + 16);
            uint4 ah = ws4[6144 + k*32 + lane];
            uint4 al = __ldg(&g_dfrag[256 + k*32 + lane]);
            MMA(dacc, ah, b0, b1);
            MMA(dacc, ah, c0, c1);
            MMA(dacc, al, b0, b1);
        }
        int i = lane >> 2;
        float w1a = dw1s[i], w1b = dw1s[i + 8];
        float b0a = db0s[i], b0b = db0s[i + 8];
        float v0 = fmaxf(dacc[0] + b0a, 0.0f)*w1a + fmaxf(dacc[2] + b0b, 0.0f)*w1b;
        float v1 = fmaxf(dacc[1] + b0a, 0.0f)*w1a + fmaxf(dacc[3] + b0b, 0.0f)*w1b;
        v0 += __shfl_xor_sync(0xffffffffu, v0, 4);
        v0 += __shfl_xor_sync(0xffffffffu, v0, 8);
        v0 += __shfl_xor_sync(0xffffffffu, v0, 16);
        v1 += __shfl_xor_sync(0xffffffffu, v1, 4);
        v1 += __shfl_xor_sync(0xffffffffu, v1, 8);
        v1 += __shfl_xor_sync(0xffffffffu, v1, 16);
        if (lane < 4) {
            int r0 = gr0 + wm*8 + lane*2;
            float o0 = v0 + db1v;
            float o1 = v1 + db1v;
            out[(u64)(row0 + r0)*50 + col] = o0;
            out[(u64)(row0 + r0 + 1)*50 + col] = o1;
            xps[r0]     = o0;
            xps[r0 + 1] = o1;
        }
    };

    float acc[3][4][4];

    // phase A: decoder (s>=1) + GRU MMA over this group's 32 rows
    auto phaseA = [&](int s) {
        if (s > 0 && wm < 4) decoder(s);
        #pragma unroll
        for (int g = 0; g < 3; ++g)
            #pragma unroll
            for (int nt = 0; nt < 4; ++nt)
                #pragma unroll
                for (int q = 0; q < 4; ++q) acc[g][nt][q] = 0.0f;
        #pragma unroll 2
        for (int k = 0; k < 8; ++k) {
            u32 bh[4][2], bl[4][2];
            #pragma unroll
            for (int nt = 0; nt < 4; ++nt) {
                int r = gr0 + nt*8 + (lane >> 2);
                int off = r*272 + k*32 + (lane & 3)*4;
                bh[nt][0] = *(const u32*)(hhi + off);
                bh[nt][1] = *(const u32*)(hhi + off + 16);
                bl[nt][0] = *(const u32*)(hlo + off);
                bl[nt][1] = *(const u32*)(hlo + off + 16);
            }
            #pragma unroll
            for (int g = 0; g < 3; ++g) {
                uint4 ah = ws4[(g*8 + wm)*256 + k*32 + lane];
                uint4 al = __ldg(&wf[6144 + (g*8 + wm)*256 + k*32 + lane]);
                #pragma unroll
                for (int nt = 0; nt < 4; ++nt) {
                    MMA(acc[g][nt], ah, bh[nt][0], bh[nt][1]);
                    MMA(acc[g][nt], ah, bl[nt][0], bl[nt][1]);
                    MMA(acc[g][nt], al, bh[nt][0], bh[nt][1]);
                }
            }
        }
    };

    // phase B: epilogue -> new h, write tiles + hold slots (group rows only)
    auto phaseB = [&]() {
        #pragma unroll
        for (int i = 0; i < 2; ++i) {
            int u = wm*16 + (lane >> 2) + 8*i;
            float wir = wihs[u], wiz = wihs[128 + u], win = wihs[256 + u];
            float br  = bihs[u]       + bhhs[u];
            float bz  = bihs[128 + u] + bhhs[128 + u];
            float bni = bihs[256 + u];
            float bnh = bhhs[256 + u];
            #pragma unroll
            for (int nt = 0; nt < 4; ++nt) {
                #pragma unroll
                for (int j = 0; j < 2; ++j) {
                    int r = gr0 + nt*8 + (lane & 3)*2 + j;
                    int q = 2*i + j;
                    int hidx = (i*8 + nt*2 + j)*512 + tid;
                    float xp   = xps[r];
                    float hold = hs[hidx];
                    float rg = sigm(acc[0][nt][q] + fmaf(xp, wir, br));
                    float zg = sigm(acc[1][nt][q] + fmaf(xp, wiz, bz));
                    float ng = tanha(fmaf(xp, win, bni) + rg*(acc[2][nt][q] + bnh));
                    float h  = (1.0f - zg)*ng + zg*hold;
                    hs[hidx] = h;
                    __nv_bfloat16 bhv = __float2bfloat16(h);
                    __nv_bfloat16 blv = __float2bfloat16(h - __bfloat162float(bhv));
                    *(__nv_bfloat16*)(hhi + r*272 + u*2) = bhv;
                    *(__nv_bfloat16*)(hlo + r*272 + u*2) = blv;
                }
            }
        }
    };

    // ---- antiphase scheduling ----
    if (grp == 0) phaseA(0);
    __syncthreads();

    if (grp == 0) {
        for (int s = 0; s < NSTEP; ++s) {
            phaseB();
            BARG(0);
            if (s < NSTEP - 1) phaseA(s + 1);
            BARG(0);
        }
        if (wm < 4) decoder(NSTEP);
    } else {
        for (int s = 0; s < NSTEP; ++s) {
            phaseA(s);
            BARG(1);
            phaseB();
            BARG(1);
        }
        if (wm < 4) decoder(NSTEP);
    }
}

extern "C" void kernel_launch(void* const* d_in, const int* in_sizes, int n_in,
                              void* d_out, int out_size) {
    (void)in_sizes; (void)n_in; (void)out_size;
    const float* x   = (const float*)d_in[0];
    const float* ew0 = (const float*)d_in[1];
    const float* eb0 = (const float*)d_in[2];
    const float* ew1 = (const float*)d_in[3];
    const float* eb1 = (const float*)d_in[4];
    const float* ew2 = (const float*)d_in[5];
    const float* eb2 = (const float*)d_in[6];
    const float* wih = (const float*)d_in[7];
    const float* whh = (const float*)d_in[8];
    const float* bih = (const float*)d_in[9];
    const float* bhh = (const float*)d_in[10];
    const float* dw0 = (const float*)d_in[11];
    const float* db0 = (const float*)d_in[12];
    const float* dw1 = (const float*)d_in[13];
    const float* db1 = (const float*)d_in[14];
    float* out = (float*)d_out;

    cudaFuncSetAttribute(gru_kernel, cudaFuncAttributeMaxDynamicSharedMemorySize, SMEM_BYTES);

    repack<<<25, 512>>>(whh, dw0);
    gru_kernel<<<NBLK, NTHR, SMEM_BYTES>>>(x, ew0, eb0, ew1, eb1, ew2, eb2,
                                           wih, whh, bih, bhh, dw0, db0, dw1, db1, out);
}

// round 13
// speedup vs baseline: 1.5327x; 1.2781x over previous
#include <cuda_runtime.h>
#include <cuda_fp16.h>

typedef unsigned int u32;
typedef unsigned long long u64;

#define NBLK  128
#define NTHR  512
#define ROWS  64
#define HPAD  132
#define NSTEP 49

// ---- dynamic smem layout (float offsets) ----
#define F_XPS   0        // 64
#define F_WIHS  64       // 384
#define F_BIHS  448      // 384
#define F_BHHS  832      // 384
#define F_DW1   1216     // 16
#define F_DB0   1232     // 16
#define F_DB1   1248     // 1 (pad to 1280)
#define F_HHI   1280     // fp16 [64][136] = 4352 floats
#define F_HLO   5632     // 4352
#define F_HS    9984     // 16*512 per-thread hold slots
#define F_WS    18176    // staged fp16 weights: 6144+256 uint4 = 25600 floats
                         // (encoder scratch ha aliases the first 8448 floats here)
#define SMEM_FLOATS 43776
#define SMEM_BYTES  (SMEM_FLOATS*4)

// GRU A fragments (fp16 weights): [g][wm][k][lane] as uint4
__device__ uint4 g_wfrag[3 * 8 * 8 * 32];
// decoder A fragments (fp16): [k][lane] as uint4 (m16 x k128)
__device__ uint4 g_dfrag[8 * 32];

#define MMA(c, a, b0v, b1v) asm volatile( \
    "mma.sync.aligned.m16n8k16.row.col.f32.f16.f16.f32 " \
    "{%0,%1,%2,%3}, {%4,%5,%6,%7}, {%8,%9}, {%0,%1,%2,%3};" \
    : "+f"((c)[0]), "+f"((c)[1]), "+f"((c)[2]), "+f"((c)[3]) \
    : "r"((a).x), "r"((a).y), "r"((a).z), "r"((a).w), "r"(b0v), "r"(b1v))

#define BARG(gid) asm volatile("bar.sync %0, %1;" :: "r"((gid) + 1), "r"(256) : "memory")

__device__ __forceinline__ float tanha(float x) {
    float y;
    asm("tanh.approx.f32 %0, %1;" : "=f"(y) : "f"(x));
    return y;
}
__device__ __forceinline__ float sigm(float x) {
    return fmaf(0.5f, tanha(0.5f * x), 0.5f);
}
__device__ __forceinline__ u32 pack_h2(__half lo, __half hi) {
    return ((u32)__half_as_ushort(hi) << 16) | (u32)__half_as_ushort(lo);
}

// ---------------- weight repack (fp16, single precision level) ----------------
__global__ void repack(const float* __restrict__ whh, const float* __restrict__ dw0) {
    int idx = blockIdx.x * blockDim.x + threadIdx.x;
    if (idx < 6144) {
        int lane = idx & 31;
        int k    = (idx >> 5) & 7;
        int wm   = (idx >> 8) & 7;
        int g    = idx >> 11;          // 0..2
        int row  = g * 128 + wm * 16 + (lane >> 2);
        int k0   = k * 16 + (lane & 3) * 2;
        u32 o[4];
        #pragma unroll
        for (int q = 0; q < 4; ++q) {
            int rr = row + 8 * (q & 1);
            int kk = k0 + 8 * (q >> 1);
            o[q] = pack_h2(__float2half(whh[rr * 128 + kk]),
                           __float2half(whh[rr * 128 + kk + 1]));
        }
        g_wfrag[idx] = make_uint4(o[0], o[1], o[2], o[3]);
    } else if (idx < 6400) {
        int local = idx - 6144;
        int lane = local & 31;
        int k    = local >> 5;         // 0..7
        int row  = lane >> 2;
        int k0   = k * 16 + (lane & 3) * 2;
        u32 o[4];
        #pragma unroll
        for (int q = 0; q < 4; ++q) {
            int rr = row + 8 * (q & 1);
            int kk = k0 + 8 * (q >> 1);
            o[q] = pack_h2(__float2half(dw0[kk * 16 + rr]),
                           __float2half(dw0[(kk + 1) * 16 + rr]));
        }
        g_dfrag[local] = make_uint4(o[0], o[1], o[2], o[3]);
    }
}

// one 128->128 encoder layer (reads/writes ha), scalar fp32
__device__ __forceinline__ void enc_layer128(const float* __restrict__ w,
                                             const float* __restrict__ b,
                                             float* ha, int p, int t, bool relu_on) {
    float acc[4][4];
    #pragma unroll
    for (int uu = 0; uu < 4; ++uu)
        #pragma unroll
        for (int m = 0; m < 4; ++m) acc[uu][m] = 0.0f;
    const float4* w4 = (const float4*)w;
    for (int k4 = 0; k4 < 32; ++k4) {
        float xa[4][4];
        #pragma unroll
        for (int m = 0; m < 4; ++m) {
            float4 v = *(const float4*)&ha[(p + 16*m)*HPAD + k4*4];
            xa[m][0] = v.x; xa[m][1] = v.y; xa[m][2] = v.z; xa[m][3] = v.w;
        }
        #pragma unroll
        for (int kk = 0; kk < 4; ++kk) {
            float4 wv = __ldg(&w4[(k4*4 + kk)*32 + t]);
            #pragma unroll
            for (int m = 0; m < 4; ++m) {
                acc[0][m] = fmaf(wv.x, xa[m][kk], acc[0][m]);
                acc[1][m] = fmaf(wv.y, xa[m][kk], acc[1][m]);
                acc[2][m] = fmaf(wv.z, xa[m][kk], acc[2][m]);
                acc[3][m] = fmaf(wv.w, xa[m][kk], acc[3][m]);
            }
        }
    }
    __syncthreads();
    #pragma unroll
    for (int uu = 0; uu < 4; ++uu) {
        int u = t*4 + uu;
        float bv = __ldg(&b[u]);
        #pragma unroll
        for (int m = 0; m < 4; ++m) {
            float v = acc[uu][m] + bv;
            ha[(p + 16*m)*HPAD + u] = relu_on ? fmaxf(v, 0.0f) : v;
        }
    }
    __syncthreads();
}

__global__ void __launch_bounds__(NTHR, 1)
gru_kernel(const float* __restrict__ x,
           const float* __restrict__ ew0, const float* __restrict__ eb0,
           const float* __restrict__ ew1, const float* __restrict__ eb1,
           const float* __restrict__ ew2, const float* __restrict__ eb2,
           const float* __restrict__ wih, const float* __restrict__ whh,
           const float* __restrict__ bih, const float* __restrict__ bhh,
           const float* __restrict__ dw0, const float* __restrict__ db0,
           const float* __restrict__ dw1, const float* __restrict__ db1,
           float* __restrict__ out) {
    extern __shared__ float sm[];
    float* xps  = sm + F_XPS;
    float* wihs = sm + F_WIHS;
    float* bihs = sm + F_BIHS;
    float* bhhs = sm + F_BHHS;
    float* dw1s = sm + F_DW1;
    float* db0s = sm + F_DB0;
    char*  hhi  = (char*)(sm + F_HHI);   // fp16 [r][136]
    char*  hlo  = (char*)(sm + F_HLO);
    float* hs   = sm + F_HS;             // hold slots [16][512]
    uint4* ws4  = (uint4*)(sm + F_WS);   // staged fp16 weight fragments
    float* ha   = sm + F_WS;             // encoder scratch aliases weight area

    const int tid  = threadIdx.x;
    const int wid  = tid >> 5;
    const int lane = tid & 31;
    const int row0 = blockIdx.x * ROWS;

    // ---- small smem init ----
    for (int j = tid; j < 384; j += NTHR) {
        wihs[j] = wih[j]; bihs[j] = bih[j]; bhhs[j] = bhh[j];
    }
    if (tid < 16) { dw1s[tid] = dw1[tid]; db0s[tid] = db0[tid]; }
    if (tid == 0) sm[F_DB1] = db1[0];
    if (tid < ROWS) {
        xps[tid] = 0.0f;
        out[(u64)(row0 + tid)*50] = 0.0f;
    }

    // ---- encoder (scalar fp32) ----
    {
        const int p = tid & 15, t = tid >> 4;
        float acc[4][4];
        #pragma unroll
        for (int uu = 0; uu < 4; ++uu)
            #pragma unroll
            for (int m = 0; m < 4; ++m) acc[uu][m] = 0.0f;
        const float4* x4  = (const float4*)x;
        const float4* w04 = (const float4*)ew0;
        for (int k4 = 0; k4 < 64; ++k4) {
            float xa[4][4];
            #pragma unroll
            for (int m = 0; m < 4; ++m) {
                float4 v = __ldg(&x4[(u64)(row0 + p + 16*m)*64 + k4]);
                xa[m][0] = v.x; xa[m][1] = v.y; xa[m][2] = v.z; xa[m][3] = v.w;
            }
            #pragma unroll
            for (int kk = 0; kk < 4; ++kk) {
                float4 wv = __ldg(&w04[(k4*4 + kk)*32 + t]);
                #pragma unroll
                for (int m = 0; m < 4; ++m) {
                    acc[0][m] = fmaf(wv.x, xa[m][kk], acc[0][m]);
                    acc[1][m] = fmaf(wv.y, xa[m][kk], acc[1][m]);
                    acc[2][m] = fmaf(wv.z, xa[m][kk], acc[2][m]);
                    acc[3][m] = fmaf(wv.w, xa[m][kk], acc[3][m]);
                }
            }
        }
        __syncthreads();
        #pragma unroll
        for (int uu = 0; uu < 4; ++uu) {
            int u = t*4 + uu;
            float bv = __ldg(&eb0[u]);
            #pragma unroll
            for (int m = 0; m < 4; ++m)
                ha[(p + 16*m)*HPAD + u] = fmaxf(acc[uu][m] + bv, 0.0f);
        }
        __syncthreads();
        enc_layer128(ew1, eb1, ha, p, t, true);
        enc_layer128(ew2, eb2, ha, p, t, false);
    }

    const int grp   = wid >> 3;     // row group: rows [grp*32, grp*32+32)
    const int wm    = wid & 7;      // unit block (16 units, all 3 gates)
    const int gr0   = grp * 32;

    // ---- h0: ha -> fp16 hi/lo tiles + hold slots ----
    for (int j = tid; j < 8192; j += NTHR) {
        int r = j >> 7, u = j & 127;
        float v = ha[r*HPAD + u];
        __half bh = __float2half(v);
        __half bl = __float2half(v - __half2float(bh));
        *(__half*)(hhi + r*272 + u*2) = bh;
        *(__half*)(hlo + r*272 + u*2) = bl;
    }
    #pragma unroll
    for (int i = 0; i < 2; ++i)
        #pragma unroll
        for (int nt = 0; nt < 4; ++nt)
            #pragma unroll
            for (int j = 0; j < 2; ++j) {
                int u = wm*16 + (lane >> 2) + 8*i;
                int r = gr0 + nt*8 + (lane & 3)*2 + j;
                hs[(i*8 + nt*2 + j)*512 + tid] = ha[r*HPAD + u];
            }
    __syncthreads();   // all reads of ha done; weight staging may overwrite it

    // ---- stage fp16 weight fragments into smem (once, reused 49 steps) ----
    for (int j = tid; j < 6144; j += NTHR) ws4[j] = __ldg(&g_wfrag[j]);
    for (int j = tid; j < 256; j += NTHR)  ws4[6144 + j] = __ldg(&g_dfrag[j]);
    __syncthreads();

    const float db1v = sm[F_DB1];

    // decoder (warps wm<4 of each group): reads tiles of own rows -> out col + xps
    auto decoder = [&](int col) {
        float dacc[4] = {0.0f, 0.0f, 0.0f, 0.0f};
        #pragma unroll
        for (int k = 0; k < 8; ++k) {
            int r = gr0 + wm*8 + (lane >> 2);
            int off = r*272 + k*32 + (lane & 3)*4;
            u32 b0 = *(const u32*)(hhi + off);
            u32 b1 = *(const u32*)(hhi + off + 16);
            u32 c0 = *(const u32*)(hlo + off);
            u32 c1 = *(const u32*)(hlo + off + 16);
            uint4 ah = ws4[6144 + k*32 + lane];
            MMA(dacc, ah, b0, b1);
            MMA(dacc, ah, c0, c1);
        }
        int i = lane >> 2;
        float w1a = dw1s[i], w1b = dw1s[i + 8];
        float b0a = db0s[i], b0b = db0s[i + 8];
        float v0 = fmaxf(dacc[0] + b0a, 0.0f)*w1a + fmaxf(dacc[2] + b0b, 0.0f)*w1b;
        float v1 = fmaxf(dacc[1] + b0a, 0.0f)*w1a + fmaxf(dacc[3] + b0b, 0.0f)*w1b;
        v0 += __shfl_xor_sync(0xffffffffu, v0, 4);
        v0 += __shfl_xor_sync(0xffffffffu, v0, 8);
        v0 += __shfl_xor_sync(0xffffffffu, v0, 16);
        v1 += __shfl_xor_sync(0xffffffffu, v1, 4);
        v1 += __shfl_xor_sync(0xffffffffu, v1, 8);
        v1 += __shfl_xor_sync(0xffffffffu, v1, 16);
        if (lane < 4) {
            int r0 = gr0 + wm*8 + lane*2;
            float o0 = v0 + db1v;
            float o1 = v1 + db1v;
            out[(u64)(row0 + r0)*50 + col] = o0;
            out[(u64)(row0 + r0 + 1)*50 + col] = o1;
            xps[r0]     = o0;
            xps[r0 + 1] = o1;
        }
    };

    float acc[3][4][4];

    // phase A: decoder (s>=1) + GRU MMA over this group's 32 rows
    auto phaseA = [&](int s) {
        if (s > 0 && wm < 4) decoder(s);
        #pragma unroll
        for (int g = 0; g < 3; ++g)
            #pragma unroll
            for (int nt = 0; nt < 4; ++nt)
                #pragma unroll
                for (int q = 0; q < 4; ++q) acc[g][nt][q] = 0.0f;
        #pragma unroll 2
        for (int k = 0; k < 8; ++k) {
            u32 bh[4][2], bl[4][2];
            #pragma unroll
            for (int nt = 0; nt < 4; ++nt) {
                int r = gr0 + nt*8 + (lane >> 2);
                int off = r*272 + k*32 + (lane & 3)*4;
                bh[nt][0] = *(const u32*)(hhi + off);
                bh[nt][1] = *(const u32*)(hhi + off + 16);
                bl[nt][0] = *(const u32*)(hlo + off);
                bl[nt][1] = *(const u32*)(hlo + off + 16);
            }
            #pragma unroll
            for (int g = 0; g < 3; ++g) {
                uint4 ah = ws4[(g*8 + wm)*256 + k*32 + lane];
                #pragma unroll
                for (int nt = 0; nt < 4; ++nt) {
                    MMA(acc[g][nt], ah, bh[nt][0], bh[nt][1]);
                    MMA(acc[g][nt], ah, bl[nt][0], bl[nt][1]);
                }
            }
        }
    };

    // phase B: epilogue -> new h, write tiles + hold slots (group rows only)
    auto phaseB = [&]() {
        #pragma unroll
        for (int i = 0; i < 2; ++i) {
            int u = wm*16 + (lane >> 2) + 8*i;
            float wir = wihs[u], wiz = wihs[128 + u], win = wihs[256 + u];
            float br  = bihs[u]       + bhhs[u];
            float bz  = bihs[128 + u] + bhhs[128 + u];
            float bni = bihs[256 + u];
            float bnh = bhhs[256 + u];
            #pragma unroll
            for (int nt = 0; nt < 4; ++nt) {
                #pragma unroll
                for (int j = 0; j < 2; ++j) {
                    int r = gr0 + nt*8 + (lane & 3)*2 + j;
                    int q = 2*i + j;
                    int hidx = (i*8 + nt*2 + j)*512 + tid;
                    float xp   = xps[r];
                    float hold = hs[hidx];
                    float rg = sigm(acc[0][nt][q] + fmaf(xp, wir, br));
                    float zg = sigm(acc[1][nt][q] + fmaf(xp, wiz, bz));
                    float ng = tanha(fmaf(xp, win, bni) + rg*(acc[2][nt][q] + bnh));
                    float h  = (1.0f - zg)*ng + zg*hold;
                    hs[hidx] = h;
                    __half bhv = __float2half(h);
                    __half blv = __float2half(h - __half2float(bhv));
                    *(__half*)(hhi + r*272 + u*2) = bhv;
                    *(__half*)(hlo + r*272 + u*2) = blv;
                }
            }
        }
    };

    // ---- antiphase scheduling ----
    if (grp == 0) phaseA(0);
    __syncthreads();

    if (grp == 0) {
        for (int s = 0; s < NSTEP; ++s) {
            phaseB();
            BARG(0);
            if (s < NSTEP - 1) phaseA(s + 1);
            BARG(0);
        }
        if (wm < 4) decoder(NSTEP);
    } else {
        for (int s = 0; s < NSTEP; ++s) {
            phaseA(s);
            BARG(1);
            phaseB();
            BARG(1);
        }
        if (wm < 4) decoder(NSTEP);
    }
}

extern "C" void kernel_launch(void* const* d_in, const int* in_sizes, int n_in,
                              void* d_out, int out_size) {
    (void)in_sizes; (void)n_in; (void)out_size;
    const float* x   = (const float*)d_in[0];
    const float* ew0 = (const float*)d_in[1];
    const float* eb0 = (const float*)d_in[2];
    const float* ew1 = (const float*)d_in[3];
    const float* eb1 = (const float*)d_in[4];
    const float* ew2 = (const float*)d_in[5];
    const float* eb2 = (const float*)d_in[6];
    const float* wih = (const float*)d_in[7];
    const float* whh = (const float*)d_in[8];
    const float* bih = (const float*)d_in[9];
    const float* bhh = (const float*)d_in[10];
    const float* dw0 = (const float*)d_in[11];
    const float* db0 = (const float*)d_in[12];
    const float* dw1 = (const float*)d_in[13];
    const float* db1 = (const float*)d_in[14];
    float* out = (float*)d_out;

    cudaFuncSetAttribute(gru_kernel, cudaFuncAttributeMaxDynamicSharedMemorySize, SMEM_BYTES);

    repack<<<13, 512>>>(whh, dw0);
    gru_kernel<<<NBLK, NTHR, SMEM_BYTES>>>(x, ew0, eb0, ew1, eb1, ew2, eb2,
                                           wih, whh, bih, bhh, dw0, db0, dw1, db1, out);
}

// round 14
// speedup vs baseline: 2.0608x; 1.3446x over previous
#include <cuda_runtime.h>
#include <cuda_fp16.h>

typedef unsigned int u32;
typedef unsigned long long u64;

#define NBLK  128
#define NTHR  512
#define ROWS  64
#define HPAD  132
#define NSTEP 49

// ---- dynamic smem layout (float offsets) ----
#define F_XPS   0        // 64
#define F_WIHS  64       // 384
#define F_BIHS  448      // 384
#define F_BHHS  832      // 384
#define F_DW1   1216     // 16
#define F_DB0   1232     // 16
#define F_DB1   1248     // 1 (pad to 1280)
#define F_HHI   1280     // fp16 [64][136] = 4352 floats
#define F_HS    9984     // 16*512 per-thread hold slots ([5632,9984) unused)
#define F_WS    18176    // staged fp16 weights: 6144+256 uint4 = 25600 floats
                         // (encoder scratch ha aliases the first 8448 floats here)
#define SMEM_FLOATS 43776
#define SMEM_BYTES  (SMEM_FLOATS*4)

// GRU A fragments (fp16 weights): [g][wm][k][lane] as uint4
__device__ uint4 g_wfrag[3 * 8 * 8 * 32];
// decoder A fragments (fp16): [k][lane] as uint4 (m16 x k128)
__device__ uint4 g_dfrag[8 * 32];

#define MMA(c, a, b0v, b1v) asm volatile( \
    "mma.sync.aligned.m16n8k16.row.col.f32.f16.f16.f32 " \
    "{%0,%1,%2,%3}, {%4,%5,%6,%7}, {%8,%9}, {%0,%1,%2,%3};" \
    : "+f"((c)[0]), "+f"((c)[1]), "+f"((c)[2]), "+f"((c)[3]) \
    : "r"((a).x), "r"((a).y), "r"((a).z), "r"((a).w), "r"(b0v), "r"(b1v))

#define BARG(gid) asm volatile("bar.sync %0, %1;" :: "r"((gid) + 1), "r"(256) : "memory")

__device__ __forceinline__ float tanha(float x) {
    float y;
    asm("tanh.approx.f32 %0, %1;" : "=f"(y) : "f"(x));
    return y;
}
__device__ __forceinline__ float sigm(float x) {
    return fmaf(0.5f, tanha(0.5f * x), 0.5f);
}
__device__ __forceinline__ u32 pack_h2(__half lo, __half hi) {
    return ((u32)__half_as_ushort(hi) << 16) | (u32)__half_as_ushort(lo);
}

// ---------------- weight repack (fp16) ----------------
__global__ void repack(const float* __restrict__ whh, const float* __restrict__ dw0) {
    int idx = blockIdx.x * blockDim.x + threadIdx.x;
    if (idx < 6144) {
        int lane = idx & 31;
        int k    = (idx >> 5) & 7;
        int wm   = (idx >> 8) & 7;
        int g    = idx >> 11;          // 0..2
        int row  = g * 128 + wm * 16 + (lane >> 2);
        int k0   = k * 16 + (lane & 3) * 2;
        u32 o[4];
        #pragma unroll
        for (int q = 0; q < 4; ++q) {
            int rr = row + 8 * (q & 1);
            int kk = k0 + 8 * (q >> 1);
            o[q] = pack_h2(__float2half(whh[rr * 128 + kk]),
                           __float2half(whh[rr * 128 + kk + 1]));
        }
        g_wfrag[idx] = make_uint4(o[0], o[1], o[2], o[3]);
    } else if (idx < 6400) {
        int local = idx - 6144;
        int lane = local & 31;
        int k    = local >> 5;         // 0..7
        int row  = lane >> 2;
        int k0   = k * 16 + (lane & 3) * 2;
        u32 o[4];
        #pragma unroll
        for (int q = 0; q < 4; ++q) {
            int rr = row + 8 * (q & 1);
            int kk = k0 + 8 * (q >> 1);
            o[q] = pack_h2(__float2half(dw0[kk * 16 + rr]),
                           __float2half(dw0[(kk + 1) * 16 + rr]));
        }
        g_dfrag[local] = make_uint4(o[0], o[1], o[2], o[3]);
    }
}

// one 128->128 encoder layer (reads/writes ha), scalar fp32
__device__ __forceinline__ void enc_layer128(const float* __restrict__ w,
                                             const float* __restrict__ b,
                                             float* ha, int p, int t, bool relu_on) {
    float acc[4][4];
    #pragma unroll
    for (int uu = 0; uu < 4; ++uu)
        #pragma unroll
        for (int m = 0; m < 4; ++m) acc[uu][m] = 0.0f;
    const float4* w4 = (const float4*)w;
    for (int k4 = 0; k4 < 32; ++k4) {
        float xa[4][4];
        #pragma unroll
        for (int m = 0; m < 4; ++m) {
            float4 v = *(const float4*)&ha[(p + 16*m)*HPAD + k4*4];
            xa[m][0] = v.x; xa[m][1] = v.y; xa[m][2] = v.z; xa[m][3] = v.w;
        }
        #pragma unroll
        for (int kk = 0; kk < 4; ++kk) {
            float4 wv = __ldg(&w4[(k4*4 + kk)*32 + t]);
            #pragma unroll
            for (int m = 0; m < 4; ++m) {
                acc[0][m] = fmaf(wv.x, xa[m][kk], acc[0][m]);
                acc[1][m] = fmaf(wv.y, xa[m][kk], acc[1][m]);
                acc[2][m] = fmaf(wv.z, xa[m][kk], acc[2][m]);
                acc[3][m] = fmaf(wv.w, xa[m][kk], acc[3][m]);
            }
        }
    }
    __syncthreads();
    #pragma unroll
    for (int uu = 0; uu < 4; ++uu) {
        int u = t*4 + uu;
        float bv = __ldg(&b[u]);
        #pragma unroll
        for (int m = 0; m < 4; ++m) {
            float v = acc[uu][m] + bv;
            ha[(p + 16*m)*HPAD + u] = relu_on ? fmaxf(v, 0.0f) : v;
        }
    }
    __syncthreads();
}

__global__ void __launch_bounds__(NTHR, 1)
gru_kernel(const float* __restrict__ x,
           const float* __restrict__ ew0, const float* __restrict__ eb0,
           const float* __restrict__ ew1, const float* __restrict__ eb1,
           const float* __restrict__ ew2, const float* __restrict__ eb2,
           const float* __restrict__ wih, const float* __restrict__ whh,
           const float* __restrict__ bih, const float* __restrict__ bhh,
           const float* __restrict__ dw0, const float* __restrict__ db0,
           const float* __restrict__ dw1, const float* __restrict__ db1,
           float* __restrict__ out) {
    extern __shared__ float sm[];
    float* xps  = sm + F_XPS;
    float* wihs = sm + F_WIHS;
    float* bihs = sm + F_BIHS;
    float* bhhs = sm + F_BHHS;
    float* dw1s = sm + F_DW1;
    float* db0s = sm + F_DB0;
    char*  hhi  = (char*)(sm + F_HHI);   // fp16 [r][136]
    float* hs   = sm + F_HS;             // hold slots [16][512]
    uint4* ws4  = (uint4*)(sm + F_WS);   // staged fp16 weight fragments
    float* ha   = sm + F_WS;             // encoder scratch aliases weight area

    const int tid  = threadIdx.x;
    const int wid  = tid >> 5;
    const int lane = tid & 31;
    const int row0 = blockIdx.x * ROWS;

    // ---- small smem init ----
    for (int j = tid; j < 384; j += NTHR) {
        wihs[j] = wih[j]; bihs[j] = bih[j]; bhhs[j] = bhh[j];
    }
    if (tid < 16) { dw1s[tid] = dw1[tid]; db0s[tid] = db0[tid]; }
    if (tid == 0) sm[F_DB1] = db1[0];
    if (tid < ROWS) {
        xps[tid] = 0.0f;
        out[(u64)(row0 + tid)*50] = 0.0f;
    }

    // ---- encoder (scalar fp32) ----
    {
        const int p = tid & 15, t = tid >> 4;
        float acc[4][4];
        #pragma unroll
        for (int uu = 0; uu < 4; ++uu)
            #pragma unroll
            for (int m = 0; m < 4; ++m) acc[uu][m] = 0.0f;
        const float4* x4  = (const float4*)x;
        const float4* w04 = (const float4*)ew0;
        for (int k4 = 0; k4 < 64; ++k4) {
            float xa[4][4];
            #pragma unroll
            for (int m = 0; m < 4; ++m) {
                float4 v = __ldg(&x4[(u64)(row0 + p + 16*m)*64 + k4]);
                xa[m][0] = v.x; xa[m][1] = v.y; xa[m][2] = v.z; xa[m][3] = v.w;
            }
            #pragma unroll
            for (int kk = 0; kk < 4; ++kk) {
                float4 wv = __ldg(&w04[(k4*4 + kk)*32 + t]);
                #pragma unroll
                for (int m = 0; m < 4; ++m) {
                    acc[0][m] = fmaf(wv.x, xa[m][kk], acc[0][m]);
                    acc[1][m] = fmaf(wv.y, xa[m][kk], acc[1][m]);
                    acc[2][m] = fmaf(wv.z, xa[m][kk], acc[2][m]);
                    acc[3][m] = fmaf(wv.w, xa[m][kk], acc[3][m]);
                }
            }
        }
        __syncthreads();
        #pragma unroll
        for (int uu = 0; uu < 4; ++uu) {
            int u = t*4 + uu;
            float bv = __ldg(&eb0[u]);
            #pragma unroll
            for (int m = 0; m < 4; ++m)
                ha[(p + 16*m)*HPAD + u] = fmaxf(acc[uu][m] + bv, 0.0f);
        }
        __syncthreads();
        enc_layer128(ew1, eb1, ha, p, t, true);
        enc_layer128(ew2, eb2, ha, p, t, false);
    }

    const int grp   = wid >> 3;     // row group: rows [grp*32, grp*32+32)
    const int wm    = wid & 7;      // unit block (16 units, all 3 gates)
    const int gr0   = grp * 32;

    // ---- h0: ha -> fp16 tile + hold slots ----
    for (int j = tid; j < 8192; j += NTHR) {
        int r = j >> 7, u = j & 127;
        float v = ha[r*HPAD + u];
        *(__half*)(hhi + r*272 + u*2) = __float2half(v);
    }
    #pragma unroll
    for (int i = 0; i < 2; ++i)
        #pragma unroll
        for (int nt = 0; nt < 4; ++nt)
            #pragma unroll
            for (int j = 0; j < 2; ++j) {
                int u = wm*16 + (lane >> 2) + 8*i;
                int r = gr0 + nt*8 + (lane & 3)*2 + j;
                hs[(i*8 + nt*2 + j)*512 + tid] = ha[r*HPAD + u];
            }
    __syncthreads();   // all reads of ha done; weight staging may overwrite it

    // ---- stage fp16 weight fragments into smem (once, reused 49 steps) ----
    for (int j = tid; j < 6144; j += NTHR) ws4[j] = __ldg(&g_wfrag[j]);
    for (int j = tid; j < 256; j += NTHR)  ws4[6144 + j] = __ldg(&g_dfrag[j]);
    __syncthreads();

    const float db1v = sm[F_DB1];

    // decoder (warps wm<4 of each group): reads tiles of own rows -> out col + xps
    auto decoder = [&](int col) {
        float dacc[4] = {0.0f, 0.0f, 0.0f, 0.0f};
        #pragma unroll
        for (int k = 0; k < 8; ++k) {
            int r = gr0 + wm*8 + (lane >> 2);
            int off = r*272 + k*32 + (lane & 3)*4;
            u32 b0 = *(const u32*)(hhi + off);
            u32 b1 = *(const u32*)(hhi + off + 16);
            uint4 ah = ws4[6144 + k*32 + lane];
            MMA(dacc, ah, b0, b1);
        }
        int i = lane >> 2;
        float w1a = dw1s[i], w1b = dw1s[i + 8];
        float b0a = db0s[i], b0b = db0s[i + 8];
        float v0 = fmaxf(dacc[0] + b0a, 0.0f)*w1a + fmaxf(dacc[2] + b0b, 0.0f)*w1b;
        float v1 = fmaxf(dacc[1] + b0a, 0.0f)*w1a + fmaxf(dacc[3] + b0b, 0.0f)*w1b;
        v0 += __shfl_xor_sync(0xffffffffu, v0, 4);
        v0 += __shfl_xor_sync(0xffffffffu, v0, 8);
        v0 += __shfl_xor_sync(0xffffffffu, v0, 16);
        v1 += __shfl_xor_sync(0xffffffffu, v1, 4);
        v1 += __shfl_xor_sync(0xffffffffu, v1, 8);
        v1 += __shfl_xor_sync(0xffffffffu, v1, 16);
        if (lane < 4) {
            int r0 = gr0 + wm*8 + lane*2;
            float o0 = v0 + db1v;
            float o1 = v1 + db1v;
            out[(u64)(row0 + r0)*50 + col] = o0;
            out[(u64)(row0 + r0 + 1)*50 + col] = o1;
            xps[r0]     = o0;
            xps[r0 + 1] = o1;
        }
    };

    float acc[3][4][4];

    // phase A: decoder (s>=1) + GRU MMA over this group's 32 rows
    auto phaseA = [&](int s) {
        if (s > 0 && wm < 4) decoder(s);
        #pragma unroll
        for (int g = 0; g < 3; ++g)
            #pragma unroll
            for (int nt = 0; nt < 4; ++nt)
                #pragma unroll
                for (int q = 0; q < 4; ++q) acc[g][nt][q] = 0.0f;
        #pragma unroll 2
        for (int k = 0; k < 8; ++k) {
            u32 bh[4][2];
            #pragma unroll
            for (int nt = 0; nt < 4; ++nt) {
                int r = gr0 + nt*8 + (lane >> 2);
                int off = r*272 + k*32 + (lane & 3)*4;
                bh[nt][0] = *(const u32*)(hhi + off);
                bh[nt][1] = *(const u32*)(hhi + off + 16);
            }
            #pragma unroll
            for (int g = 0; g < 3; ++g) {
                uint4 ah = ws4[(g*8 + wm)*256 + k*32 + lane];
                #pragma unroll
                for (int nt = 0; nt < 4; ++nt)
                    MMA(acc[g][nt], ah, bh[nt][0], bh[nt][1]);
            }
        }
    };

    // phase B: epilogue -> new h, write tile + hold slots (group rows only)
    auto phaseB = [&]() {
        #pragma unroll
        for (int i = 0; i < 2; ++i) {
            int u = wm*16 + (lane >> 2) + 8*i;
            float wir = wihs[u], wiz = wihs[128 + u], win = wihs[256 + u];
            float br  = bihs[u]       + bhhs[u];
            float bz  = bihs[128 + u] + bhhs[128 + u];
            float bni = bihs[256 + u];
            float bnh = bhhs[256 + u];
            #pragma unroll
            for (int nt = 0; nt < 4; ++nt) {
                #pragma unroll
                for (int j = 0; j < 2; ++j) {
                    int r = gr0 + nt*8 + (lane & 3)*2 + j;
                    int q = 2*i + j;
                    int hidx = (i*8 + nt*2 + j)*512 + tid;
                    float xp   = xps[r];
                    float hold = hs[hidx];
                    float rg = sigm(acc[0][nt][q] + fmaf(xp, wir, br));
                    float zg = sigm(acc[1][nt][q] + fmaf(xp, wiz, bz));
                    float ng = tanha(fmaf(xp, win, bni) + rg*(acc[2][nt][q] + bnh));
                    float h  = (1.0f - zg)*ng + zg*hold;
                    hs[hidx] = h;
                    *(__half*)(hhi + r*272 + u*2) = __float2half(h);
                }
            }
        }
    };

    // ---- antiphase scheduling ----
    if (grp == 0) phaseA(0);
    __syncthreads();

    if (grp == 0) {
        for (int s = 0; s < NSTEP; ++s) {
            phaseB();
            BARG(0);
            if (s < NSTEP - 1) phaseA(s + 1);
            BARG(0);
        }
        if (wm < 4) decoder(NSTEP);
    } else {
        for (int s = 0; s < NSTEP; ++s) {
            phaseA(s);
            BARG(1);
            phaseB();
            BARG(1);
        }
        if (wm < 4) decoder(NSTEP);
    }
}

extern "C" void kernel_launch(void* const* d_in, const int* in_sizes, int n_in,
                              void* d_out, int out_size) {
    (void)in_sizes; (void)n_in; (void)out_size;
    const float* x   = (const float*)d_in[0];
    const float* ew0 = (const float*)d_in[1];
    const float* eb0 = (const float*)d_in[2];
    const float* ew1 = (const float*)d_in[3];
    const float* eb1 = (const float*)d_in[4];
    const float* ew2 = (const float*)d_in[5];
    const float* eb2 = (const float*)d_in[6];
    const float* wih = (const float*)d_in[7];
    const float* whh = (const float*)d_in[8];
    const float* bih = (const float*)d_in[9];
    const float* bhh = (const float*)d_in[10];
    const float* dw0 = (const float*)d_in[11];
    const float* db0 = (const float*)d_in[12];
    const float* dw1 = (const float*)d_in[13];
    const float* db1 = (const float*)d_in[14];
    float* out = (float*)d_out;

    cudaFuncSetAttribute(gru_kernel, cudaFuncAttributeMaxDynamicSharedMemorySize, SMEM_BYTES);

    repack<<<13, 512>>>(whh, dw0);
    gru_kernel<<<NBLK, NTHR, SMEM_BYTES>>>(x, ew0, eb0, ew1, eb1, ew2, eb2,
                                           wih, whh, bih, bhh, dw0, db0, dw1, db1, out);
}